// round 2
// baseline (speedup 1.0000x reference)
#include <cuda_runtime.h>
#include <cuda_bf16.h>

// ---------------- scratch (device globals; no allocation) ----------------
__device__ float g_out1[4096 * 32];        // conv1 out, [pixel][oc]
__device__ float g_c2[64 * 62 * 62];       // conv2 out, [oc][i][j]
__device__ float g_pool[64 * 61 * 61];     // pooled, flat-index order
__device__ float g_r128[128];              // flat @ D1
__device__ float g_rt[256];
__device__ float g_qt[256];
__device__ float g_st[256];
__device__ float g_scores[4096];
__device__ float g_smax[2];                // max, sumexp
__device__ float g_ct[256];

#define NFLAT 238144   // 64*61*61

// ---------------- zero-init accumulators ----------------
__global__ void zero_kernel() {
    int i = blockIdx.x * blockDim.x + threadIdx.x;
    if (i < 4096 * 32) g_out1[i] = 0.f;
    if (i < 128) g_r128[i] = 0.f;
    if (i < 256) g_ct[i] = 0.f;
}

// ---------------- conv1: SAME 3x3, 256 -> 32, 64x64 ----------------
// grid (64 rows, 4 ic-quarters), block 128. Thread tile 4px x 4oc.
__global__ __launch_bounds__(128) void conv1_kernel(const float* __restrict__ mem,
                                                    const float* __restrict__ K1) {
    int h   = blockIdx.x;
    int icq = blockIdx.y;           // each block handles 64 input channels
    int tid = threadIdx.x;
    int pg  = tid & 15;             // 16 pixel groups * 4 px = 64 px (full row)
    int og  = tid >> 4;             // 8 oc groups * 4 oc = 32 oc

    __shared__ float sIn[32 * 67];  // [ic][col 0..65], stride 67 (conflict-free)
    __shared__ float sW[3 * 32 * 32];  // [kw][ic][oc]

    float acc[4][4];
#pragma unroll
    for (int a = 0; a < 4; a++)
#pragma unroll
        for (int b = 0; b < 4; b++) acc[a][b] = 0.f;

    for (int kh = 0; kh < 3; kh++) {
        int r = h + kh - 1;
        if (r < 0 || r > 63) continue;
        for (int ch = 0; ch < 2; ch++) {
            int ic0 = icq * 64 + ch * 32;
            __syncthreads();
            // stage input: 32 ic x 66 cols (zero-padded edges)
            for (int t = tid; t < 32 * 66; t += 128) {
                int ic = t & 31;
                int c  = t >> 5;          // 0..65  -> input col c-1
                float v = 0.f;
                int col = c - 1;
                if (col >= 0 && col < 64) v = mem[(r * 64 + col) * 256 + ic0 + ic];
                sIn[ic * 67 + c] = v;
            }
            // stage weights: 3 kw x 32 ic x 32 oc
            for (int t = tid; t < 3 * 32 * 32; t += 128) {
                int oc = t & 31;
                int ic = (t >> 5) & 31;
                int kw = t >> 10;
                sW[t] = K1[((kh * 3 + kw) * 256 + ic0 + ic) * 32 + oc];
            }
            __syncthreads();
#pragma unroll 4
            for (int ic = 0; ic < 32; ic++) {
#pragma unroll
                for (int kw = 0; kw < 3; kw++) {
                    const float* wp = &sW[(kw * 32 + ic) * 32 + og * 4];
                    float w0 = wp[0], w1 = wp[1], w2 = wp[2], w3 = wp[3];
                    const float* xp = &sIn[ic * 67 + pg * 4 + kw];
                    float x0 = xp[0], x1 = xp[1], x2 = xp[2], x3 = xp[3];
                    acc[0][0] += x0 * w0; acc[0][1] += x0 * w1; acc[0][2] += x0 * w2; acc[0][3] += x0 * w3;
                    acc[1][0] += x1 * w0; acc[1][1] += x1 * w1; acc[1][2] += x1 * w2; acc[1][3] += x1 * w3;
                    acc[2][0] += x2 * w0; acc[2][1] += x2 * w1; acc[2][2] += x2 * w2; acc[2][3] += x2 * w3;
                    acc[3][0] += x3 * w0; acc[3][1] += x3 * w1; acc[3][2] += x3 * w2; acc[3][3] += x3 * w3;
                }
            }
        }
    }
#pragma unroll
    for (int a = 0; a < 4; a++) {
        int px = pg * 4 + a;
#pragma unroll
        for (int b = 0; b < 4; b++)
            atomicAdd(&g_out1[(h * 64 + px) * 32 + og * 4 + b], acc[a][b]);
    }
}

// ---------------- conv2: VALID 3x3, 32 -> 64, 64x64 -> 62x62 ----------------
// grid 62 (output rows), block 256, dynamic smem. Thread tile 2px x 8oc.
__global__ __launch_bounds__(256) void conv2_kernel(const float* __restrict__ K2) {
    extern __shared__ float smem2[];
    float* sIn = smem2;               // 3 rows x 32 ic x 65 cols = 6240 floats
    float* sW  = smem2 + 6240;        // 9*32*64 = 18432 floats

    int i = blockIdx.x;               // 0..61
    int tid = threadIdx.x;
    int pxg = tid & 31;               // 31 valid groups of 2 px
    int ocg = tid >> 5;               // 8 groups of 8 oc (warp-uniform)

    for (int t = tid; t < 3 * 64 * 32; t += 256) {
        int ic  = t & 31;
        int col = (t >> 5) & 63;
        int rr  = t >> 11;
        sIn[(rr * 32 + ic) * 65 + col] = g_out1[((i + rr) * 64 + col) * 32 + ic];
    }
    for (int t = tid; t < 9 * 32 * 64; t += 256) sW[t] = K2[t];
    __syncthreads();

    if (pxg < 31) {
        int px = pxg * 2;
        float acc[2][8];
#pragma unroll
        for (int a = 0; a < 2; a++)
#pragma unroll
            for (int b = 0; b < 8; b++) acc[a][b] = 0.f;

        for (int kh = 0; kh < 3; kh++)
            for (int ic = 0; ic < 32; ic++) {
#pragma unroll
                for (int kw = 0; kw < 3; kw++) {
                    float x0 = sIn[(kh * 32 + ic) * 65 + px + kw];
                    float x1 = sIn[(kh * 32 + ic) * 65 + px + 1 + kw];
                    const float* wp = &sW[((kh * 3 + kw) * 32 + ic) * 64 + ocg * 8];
#pragma unroll
                    for (int b = 0; b < 8; b++) {
                        float w = wp[b];
                        acc[0][b] += x0 * w;
                        acc[1][b] += x1 * w;
                    }
                }
            }
#pragma unroll
        for (int b = 0; b < 8; b++)
#pragma unroll
            for (int a = 0; a < 2; a++)
                g_c2[(ocg * 8 + b) * 3844 + i * 62 + px + a] = acc[a][b];
    }
}

// ---------------- pool: 2x2 mean (stride 1) into flat order ----------------
__global__ void pool_kernel() {
    int f = blockIdx.x * blockDim.x + threadIdx.x;
    if (f >= NFLAT) return;
    int j = f % 61;
    int t = f / 61;
    int i = t % 61;
    int oc = t / 61;
    const float* p = &g_c2[oc * 3844 + i * 62 + j];
    g_pool[f] = 0.25f * (p[0] + p[1] + p[62] + p[63]);
}

// ---------------- GEMV: r128 = flat @ D1 (238144 x 128) ----------------
__global__ __launch_bounds__(128) void gemv_d1_kernel(const float* __restrict__ D1) {
    int k = threadIdx.x;
    long f0 = (long)blockIdx.x * 256;
    long fend = f0 + 256;
    if (fend > NFLAT) fend = NFLAT;
    float a0 = 0.f, a1 = 0.f, a2 = 0.f, a3 = 0.f;
    long f = f0;
    for (; f + 4 <= fend; f += 4) {
        float p0 = g_pool[f], p1 = g_pool[f + 1], p2 = g_pool[f + 2], p3 = g_pool[f + 3];
        a0 += p0 * D1[f * 128 + k];
        a1 += p1 * D1[(f + 1) * 128 + k];
        a2 += p2 * D1[(f + 2) * 128 + k];
        a3 += p3 * D1[(f + 3) * 128 + k];
    }
    for (; f < fend; f++) a0 += g_pool[f] * D1[f * 128 + k];
    atomicAdd(&g_r128[k], a0 + a1 + a2 + a3);
}

// ---------------- small dense chain: r_t, q_t, s_t ----------------
__global__ __launch_bounds__(256) void small_d_kernel(const float* __restrict__ inp,
                                                      const float* __restrict__ D2,
                                                      const float* __restrict__ CK,
                                                      const float* __restrict__ REC) {
    __shared__ float s128[128], sin_[128], srt[256];
    int j = threadIdx.x;
    if (j < 128) { s128[j] = g_r128[j]; sin_[j] = inp[j]; }
    __syncthreads();
    float acc = 0.f;
#pragma unroll 8
    for (int k = 0; k < 128; k++) acc += s128[k] * D2[k * 256 + j];
    g_rt[j] = acc;
    srt[j] = acc;
    __syncthreads();
    float q = 0.f, s = 0.f;
#pragma unroll 4
    for (int k = 0; k < 128; k++) {
        float iv = sin_[k];
        q += iv * CK[k * 256 + j];
        s += iv * REC[k * 256 + j];
    }
#pragma unroll 4
    for (int k = 0; k < 256; k++) q += srt[k] * CK[(128 + k) * 256 + j];
    g_qt[j] = q;
    g_st[j] = s;
}

// ---------------- scores: q_t @ memory^T (4096 dots of 256) ----------------
__global__ __launch_bounds__(256) void scores_kernel(const float* __restrict__ mem) {
    __shared__ float q[256];
    int tid = threadIdx.x;
    q[tid] = g_qt[tid];
    __syncthreads();
    int warp = tid >> 5, lane = tid & 31;
    int pbase = blockIdx.x * 32 + warp * 4;
#pragma unroll
    for (int u = 0; u < 4; u++) {
        int p = pbase + u;
        float acc = 0.f;
#pragma unroll
        for (int t = 0; t < 8; t++) acc += q[lane + t * 32] * mem[p * 256 + lane + t * 32];
#pragma unroll
        for (int off = 16; off; off >>= 1) acc += __shfl_down_sync(0xFFFFFFFFu, acc, off);
        if (lane == 0) g_scores[p] = acc;
    }
}

// ---------------- softmax stats ----------------
__global__ __launch_bounds__(256) void smax_kernel() {
    __shared__ float red[256];
    int tid = threadIdx.x;
    float mx = -1e30f;
    for (int p = tid; p < 4096; p += 256) mx = fmaxf(mx, g_scores[p]);
    red[tid] = mx;
    __syncthreads();
    for (int s = 128; s; s >>= 1) { if (tid < s) red[tid] = fmaxf(red[tid], red[tid + s]); __syncthreads(); }
    mx = red[0];
    __syncthreads();
    float sum = 0.f;
    for (int p = tid; p < 4096; p += 256) sum += expf(g_scores[p] - mx);
    red[tid] = sum;
    __syncthreads();
    for (int s = 128; s; s >>= 1) { if (tid < s) red[tid] += red[tid + s]; __syncthreads(); }
    if (tid == 0) { g_smax[0] = mx; g_smax[1] = red[0]; }
}

// ---------------- c_t = softmax(scores) @ memory ----------------
__global__ __launch_bounds__(256) void ct_kernel(const float* __restrict__ mem) {
    __shared__ float w[128];
    int tid = threadIdx.x;
    int pbase = blockIdx.x * 128;
    float mx = g_smax[0];
    float inv = 1.0f / g_smax[1];
    if (tid < 128) w[tid] = expf(g_scores[pbase + tid] - mx) * inv;
    __syncthreads();
    float acc = 0.f;
#pragma unroll 4
    for (int t = 0; t < 128; t++) acc += w[t] * mem[(pbase + t) * 256 + tid];
    atomicAdd(&g_ct[tid], acc);
}

// ---------------- new_mem = memory^T (tiled transpose into out) ----------------
__global__ void transpose_kernel(const float* __restrict__ mem, float* __restrict__ out) {
    __shared__ float tile[32][33];
    int p0 = blockIdx.x * 32, c0 = blockIdx.y * 32;
    int tx = threadIdx.x, ty = threadIdx.y;   // 32 x 8
#pragma unroll
    for (int r = 0; r < 32; r += 8) tile[ty + r][tx] = mem[(p0 + ty + r) * 256 + c0 + tx];
    __syncthreads();
#pragma unroll
    for (int r = 0; r < 32; r += 8)
        out[512 + (long)(c0 + ty + r) * 4096 + p0 + tx] = tile[tx][ty + r];
}

// ---------------- final: importances, memory write, outputs ----------------
__global__ __launch_bounds__(256) void final_kernel(const float* __restrict__ mem,
                                                    const float* __restrict__ REC,
                                                    const int* __restrict__ xp,
                                                    const int* __restrict__ yp,
                                                    float* __restrict__ out) {
    __shared__ float st[256], ct[256], rt[256], mc[256], red[256];
    __shared__ float ratio_s;
    int j = threadIdx.x;
    int pix = xp[0] * 64 + yp[0];
    st[j] = g_st[j];
    ct[j] = g_ct[j];
    rt[j] = g_rt[j];
    mc[j] = mem[pix * 256 + j];
    __syncthreads();
    red[j] = st[j] * ct[j];
    __syncthreads();
    for (int s = 128; s; s >>= 1) { if (j < s) red[j] += red[j + s]; __syncthreads(); }
    float local_imp = red[0];
    __syncthreads();
    red[j] = st[j] * rt[j];
    __syncthreads();
    for (int s = 128; s; s >>= 1) { if (j < s) red[j] += red[j + s]; __syncthreads(); }
    if (j == 0) ratio_s = local_imp / (local_imp + red[0]);
    __syncthreads();
    float ratio = ratio_s;
    float d = 0.f;
#pragma unroll 8
    for (int c = 0; c < 256; c++) d += (mc[c] - st[c]) * REC[(128 + c) * 256 + j];
    float val = mc[j] + ratio * d;
    out[j] = ct[j];
    out[256 + j] = rt[j];
    out[512 + (long)j * 4096 + pix] = val;
}

// ---------------- launch ----------------
extern "C" void kernel_launch(void* const* d_in, const int* in_sizes, int n_in,
                              void* d_out, int out_size) {
    const float* inputs = (const float*)d_in[0];
    const float* memory = (const float*)d_in[1];
    const float* K1     = (const float*)d_in[2];
    const float* K2     = (const float*)d_in[3];
    const float* D1     = (const float*)d_in[4];
    const float* D2     = (const float*)d_in[5];
    const float* CK     = (const float*)d_in[6];
    const float* REC    = (const float*)d_in[7];
    const int*   xp     = (const int*)d_in[8];
    const int*   yp     = (const int*)d_in[9];
    float* out = (float*)d_out;

    cudaFuncSetAttribute(conv2_kernel, cudaFuncAttributeMaxDynamicSharedMemorySize, 24672 * 4);

    zero_kernel<<<512, 256>>>();
    conv1_kernel<<<dim3(64, 4), 128>>>(memory, K1);
    conv2_kernel<<<62, 256, 24672 * 4>>>(K2);
    pool_kernel<<<(NFLAT + 255) / 256, 256>>>();
    gemv_d1_kernel<<<931, 128>>>(D1);
    small_d_kernel<<<1, 256>>>(inputs, D2, CK, REC);
    scores_kernel<<<128, 256>>>(memory);
    smax_kernel<<<1, 256>>>();
    ct_kernel<<<32, 256>>>(memory);
    transpose_kernel<<<dim3(128, 8), dim3(32, 8)>>>(memory, out);
    final_kernel<<<1, 256>>>(memory, REC, xp, yp, out);
}

// round 3
// speedup vs baseline: 1.0303x; 1.0303x over previous
#include <cuda_runtime.h>
#include <cuda_bf16.h>

#define NFLAT 238144   // 64*61*61

// ---------------- scratch (device globals; no allocation) ----------------
__device__ float g_out1p[4 * 4096 * 32];   // conv1 partials per ic-quarter, [q][pixel][oc]
__device__ float g_c2[64 * 62 * 62];       // conv2 out, [oc][i][j]
__device__ float g_r128[128];
__device__ float g_rt[256];
__device__ float g_qt[256];
__device__ float g_st[256];
__device__ float g_scores[4096];
__device__ float g_smax[2];
__device__ float g_ct[256];

// ---------------- packed fp32x2 helpers ----------------
typedef unsigned long long ull;
__device__ __forceinline__ ull pack2(float lo, float hi) {
    ull r; asm("mov.b64 %0, {%1,%2};" : "=l"(r) : "f"(lo), "f"(hi)); return r;
}
__device__ __forceinline__ void unpack2(ull v, float& lo, float& hi) {
    asm("mov.b64 {%0,%1}, %2;" : "=f"(lo), "=f"(hi) : "l"(v));
}
__device__ __forceinline__ void fma2(ull& d, ull a, ull b) {
    asm("fma.rn.f32x2 %0, %1, %2, %0;" : "+l"(d) : "l"(a), "l"(b));
}

// ---------------- conv1: SAME 3x3, 256 -> 32, 64x64 ----------------
// grid (64 rows, 4 ic-quarters), block 256. Thread tile 4px x 2oc (1 f32x2 pair).
__global__ __launch_bounds__(256) void conv1_kernel(const float* __restrict__ mem,
                                                    const float* __restrict__ K1) {
    int h   = blockIdx.x;
    int icq = blockIdx.y;
    int tid = threadIdx.x;
    int pg  = tid & 15;             // 16 pixel groups * 4 px = 64 px
    int og  = tid >> 4;             // 16 oc groups * 2 oc = 32 oc

    __shared__ float sIn[32 * 67];      // [ic][col 0..65]
    __shared__ float sW[3 * 32 * 32];   // [kw][ic][oc]

    ull acc[4] = {0ull, 0ull, 0ull, 0ull};

    for (int kh = 0; kh < 3; kh++) {
        int r = h + kh - 1;
        if (r < 0 || r > 63) continue;
        for (int ch = 0; ch < 2; ch++) {
            int ic0 = icq * 64 + ch * 32;
            __syncthreads();
            for (int t = tid; t < 32 * 66; t += 256) {
                int ic = t & 31;
                int c  = t >> 5;
                float v = 0.f;
                int col = c - 1;
                if (col >= 0 && col < 64) v = mem[(r * 64 + col) * 256 + ic0 + ic];
                sIn[ic * 67 + c] = v;
            }
            for (int t = tid; t < 3 * 32 * 32; t += 256) {
                int oc = t & 31;
                int ic = (t >> 5) & 31;
                int kw = t >> 10;
                sW[t] = K1[((kh * 3 + kw) * 256 + ic0 + ic) * 32 + oc];
            }
            __syncthreads();
#pragma unroll 4
            for (int ic = 0; ic < 32; ic++) {
                float xv[6];
#pragma unroll
                for (int c = 0; c < 6; c++) xv[c] = sIn[ic * 67 + pg * 4 + c];
                ull xb[6];
#pragma unroll
                for (int c = 0; c < 6; c++) xb[c] = pack2(xv[c], xv[c]);
#pragma unroll
                for (int kw = 0; kw < 3; kw++) {
                    ull w = *(const ull*)&sW[(kw * 32 + ic) * 32 + og * 2];
                    fma2(acc[0], xb[kw + 0], w);
                    fma2(acc[1], xb[kw + 1], w);
                    fma2(acc[2], xb[kw + 2], w);
                    fma2(acc[3], xb[kw + 3], w);
                }
            }
        }
    }
    float* dst = g_out1p + icq * 131072 + (h * 64) * 32;
#pragma unroll
    for (int a = 0; a < 4; a++) {
        float lo, hi;
        unpack2(acc[a], lo, hi);
        int px = pg * 4 + a;
        dst[px * 32 + og * 2 + 0] = lo;
        dst[px * 32 + og * 2 + 1] = hi;
    }
}

// ---------------- conv2: VALID 3x3, 32 -> 64, 64x64 -> 62x62 ----------------
// grid (62 rows, 2 oc-halves), block 256, dynamic smem. Thread tile 2px x 4oc (2 pairs).
// Staging sums the 4 conv1 ic-partials. Block (0,0) also zeroes g_r128.
__global__ __launch_bounds__(256) void conv2_kernel(const float* __restrict__ K2) {
    extern __shared__ float sm2[];
    float* sIn = sm2;                 // 3 rows x 32 ic x 65 = 6240 floats
    float* sW  = sm2 + 6240;          // 9 x 32 x 32 = 9216 floats

    int i    = blockIdx.x;            // 0..61
    int half = blockIdx.y;            // oc half
    int tid  = threadIdx.x;
    if (i == 0 && half == 0 && tid < 128) g_r128[tid] = 0.f;

    int pxg = tid & 31;
    int ocg = tid >> 5;               // 8 groups * 4 oc

    for (int t = tid; t < 3 * 64 * 32; t += 256) {
        int ic  = t & 31;
        int col = (t >> 5) & 63;
        int rr  = t >> 11;
        const float* p = g_out1p + ((i + rr) * 64 + col) * 32 + ic;
        sIn[(rr * 32 + ic) * 65 + col] = p[0] + p[131072] + p[262144] + p[393216];
    }
    for (int t = tid; t < 9 * 32 * 32; t += 256) {
        int ocl = t & 31;
        int ic  = (t >> 5) & 31;
        int kk  = t >> 10;            // kh*3+kw
        sW[t] = K2[(kk * 32 + ic) * 64 + half * 32 + ocl];
    }
    __syncthreads();

    if (pxg < 31) {
        int px = pxg * 2;
        ull acc[2][2] = {{0ull, 0ull}, {0ull, 0ull}};
        for (int kh = 0; kh < 3; kh++) {
#pragma unroll 4
            for (int ic = 0; ic < 32; ic++) {
                float xv[4];
#pragma unroll
                for (int c = 0; c < 4; c++) xv[c] = sIn[(kh * 32 + ic) * 65 + px + c];
                ull xb[4];
#pragma unroll
                for (int c = 0; c < 4; c++) xb[c] = pack2(xv[c], xv[c]);
#pragma unroll
                for (int kw = 0; kw < 3; kw++) {
                    const ull* wp = (const ull*)&sW[((kh * 3 + kw) * 32 + ic) * 32 + ocg * 4];
                    ull w0 = wp[0], w1 = wp[1];
                    fma2(acc[0][0], xb[kw + 0], w0);
                    fma2(acc[0][1], xb[kw + 0], w1);
                    fma2(acc[1][0], xb[kw + 1], w0);
                    fma2(acc[1][1], xb[kw + 1], w1);
                }
            }
        }
#pragma unroll
        for (int a = 0; a < 2; a++)
#pragma unroll
            for (int b = 0; b < 2; b++) {
                float lo, hi;
                unpack2(acc[a][b], lo, hi);
                int oc = half * 32 + ocg * 4 + b * 2;
                g_c2[(oc + 0) * 3844 + i * 62 + px + a] = lo;
                g_c2[(oc + 1) * 3844 + i * 62 + px + a] = hi;
            }
    }
}

// ---------------- GEMV with fused 2x2 mean pool: r128 += flat @ D1 ----------------
__global__ __launch_bounds__(128) void gemv_d1_kernel(const float* __restrict__ D1) {
    __shared__ float sp[256];
    int fbase = blockIdx.x * 256;
    int n = NFLAT - fbase; if (n > 256) n = 256;
    for (int t = threadIdx.x; t < 256; t += 128) {
        float v = 0.f;
        if (t < n) {
            int f  = fbase + t;
            int j  = f % 61;
            int q  = f / 61;
            int ii = q % 61;
            int oc = q / 61;
            const float* p = &g_c2[oc * 3844 + ii * 62 + j];
            v = 0.25f * (p[0] + p[1] + p[62] + p[63]);
        }
        sp[t] = v;
    }
    __syncthreads();
    int k = threadIdx.x;
    const float* Dp = D1 + (long)fbase * 128 + k;
    float a0 = 0.f, a1 = 0.f, a2 = 0.f, a3 = 0.f;
    int u = 0;
    for (; u + 8 <= n; u += 8) {
        a0 += sp[u + 0] * Dp[(long)(u + 0) * 128] + sp[u + 4] * Dp[(long)(u + 4) * 128];
        a1 += sp[u + 1] * Dp[(long)(u + 1) * 128] + sp[u + 5] * Dp[(long)(u + 5) * 128];
        a2 += sp[u + 2] * Dp[(long)(u + 2) * 128] + sp[u + 6] * Dp[(long)(u + 6) * 128];
        a3 += sp[u + 3] * Dp[(long)(u + 3) * 128] + sp[u + 7] * Dp[(long)(u + 7) * 128];
    }
    for (; u < n; u++) a0 += sp[u] * Dp[(long)u * 128];
    atomicAdd(&g_r128[k], a0 + a1 + a2 + a3);
}

// ---------------- r_t = r128 @ D2 ----------------
__global__ __launch_bounds__(128) void rt_kernel(const float* __restrict__ D2) {
    __shared__ float r[128];
    int tid = threadIdx.x;
    r[tid] = g_r128[tid];
    __syncthreads();
    int j = blockIdx.x * 128 + tid;
    float acc = 0.f;
#pragma unroll 8
    for (int k = 0; k < 128; k++) acc += r[k] * D2[k * 256 + j];
    g_rt[j] = acc;
}

// ---------------- q_t and s_t ----------------
__global__ __launch_bounds__(128) void qs_kernel(const float* __restrict__ inp,
                                                 const float* __restrict__ CK,
                                                 const float* __restrict__ REC) {
    __shared__ float si[128], sr[256];
    int tid  = threadIdx.x;
    int role = blockIdx.x >> 1;
    int j    = (blockIdx.x & 1) * 128 + tid;
    si[tid] = inp[tid];
    if (role == 0) { sr[tid] = g_rt[tid]; sr[128 + tid] = g_rt[128 + tid]; }
    __syncthreads();
    if (role == 0) {
        float q = 0.f;
#pragma unroll 4
        for (int k = 0; k < 128; k++) q += si[k] * CK[k * 256 + j];
#pragma unroll 4
        for (int c = 0; c < 256; c++) q += sr[c] * CK[(128 + c) * 256 + j];
        g_qt[j] = q;
    } else {
        float s = 0.f;
#pragma unroll 4
        for (int k = 0; k < 128; k++) s += si[k] * REC[k * 256 + j];
        g_st[j] = s;
    }
}

// ---------------- scores: q_t @ memory^T ----------------
__global__ __launch_bounds__(256) void scores_kernel(const float* __restrict__ mem) {
    __shared__ float q[256];
    int tid = threadIdx.x;
    q[tid] = g_qt[tid];
    __syncthreads();
    int warp = tid >> 5, lane = tid & 31;
    int pbase = blockIdx.x * 32 + warp * 4;
#pragma unroll
    for (int u = 0; u < 4; u++) {
        int p = pbase + u;
        float acc = 0.f;
#pragma unroll
        for (int t = 0; t < 8; t++) acc += q[lane + t * 32] * mem[p * 256 + lane + t * 32];
#pragma unroll
        for (int off = 16; off; off >>= 1) acc += __shfl_down_sync(0xFFFFFFFFu, acc, off);
        if (lane == 0) g_scores[p] = acc;
    }
}

// ---------------- softmax stats (+ zero g_ct for the next kernel) ----------------
__global__ __launch_bounds__(256) void smax_kernel() {
    __shared__ float red[256];
    int tid = threadIdx.x;
    g_ct[tid] = 0.f;
    float mx = -1e30f;
    for (int p = tid; p < 4096; p += 256) mx = fmaxf(mx, g_scores[p]);
    red[tid] = mx;
    __syncthreads();
    for (int s = 128; s; s >>= 1) { if (tid < s) red[tid] = fmaxf(red[tid], red[tid + s]); __syncthreads(); }
    mx = red[0];
    __syncthreads();
    float sum = 0.f;
    for (int p = tid; p < 4096; p += 256) sum += expf(g_scores[p] - mx);
    red[tid] = sum;
    __syncthreads();
    for (int s = 128; s; s >>= 1) { if (tid < s) red[tid] += red[tid + s]; __syncthreads(); }
    if (tid == 0) { g_smax[0] = mx; g_smax[1] = red[0]; }
}

// ---------------- fused transpose (new_mem) + c_t accumulation ----------------
__global__ void trans_ct_kernel(const float* __restrict__ mem, float* __restrict__ out) {
    __shared__ float tile[32][33];
    __shared__ float w[32];
    __shared__ float part[8][33];
    int p0 = blockIdx.x * 32, c0 = blockIdx.y * 32;
    int tx = threadIdx.x, ty = threadIdx.y;   // 32 x 8
#pragma unroll
    for (int r = 0; r < 32; r += 8) tile[ty + r][tx] = mem[(p0 + ty + r) * 256 + c0 + tx];
    if (ty == 0) w[tx] = expf(g_scores[p0 + tx] - g_smax[0]) / g_smax[1];
    __syncthreads();
#pragma unroll
    for (int r = 0; r < 32; r += 8)
        out[512 + (long)(c0 + ty + r) * 4096 + p0 + tx] = tile[tx][ty + r];
    float s = 0.f;
#pragma unroll
    for (int r = 0; r < 4; r++) s += w[ty + r * 8] * tile[ty + r * 8][tx];
    part[ty][tx] = s;
    __syncthreads();
    if (ty == 0) {
        float tot = 0.f;
#pragma unroll
        for (int y = 0; y < 8; y++) tot += part[y][tx];
        atomicAdd(&g_ct[c0 + tx], tot);
    }
}

// ---------------- final: importances, memory write, small outputs ----------------
__global__ __launch_bounds__(128) void final_kernel(const float* __restrict__ mem,
                                                    const float* __restrict__ REC,
                                                    const int* __restrict__ xp,
                                                    const int* __restrict__ yp,
                                                    float* __restrict__ out) {
    __shared__ float st[256], ct[256], rt[256], mc[256], red[128];
    __shared__ float ratio_s;
    int tid = threadIdx.x;
    int pix = xp[0] * 64 + yp[0];
    for (int t = tid; t < 256; t += 128) {
        st[t] = g_st[t];
        ct[t] = g_ct[t];
        rt[t] = g_rt[t];
        mc[t] = mem[pix * 256 + t];
    }
    __syncthreads();
    red[tid] = st[tid] * ct[tid] + st[tid + 128] * ct[tid + 128];
    __syncthreads();
    for (int s = 64; s; s >>= 1) { if (tid < s) red[tid] += red[tid + s]; __syncthreads(); }
    float local_imp = red[0];
    __syncthreads();
    red[tid] = st[tid] * rt[tid] + st[tid + 128] * rt[tid + 128];
    __syncthreads();
    for (int s = 64; s; s >>= 1) { if (tid < s) red[tid] += red[tid + s]; __syncthreads(); }
    if (tid == 0) ratio_s = local_imp / (local_imp + red[0]);
    __syncthreads();
    float ratio = ratio_s;
    int j = blockIdx.x * 128 + tid;
    float d = 0.f;
#pragma unroll 8
    for (int c = 0; c < 256; c++) d += (mc[c] - st[c]) * REC[(128 + c) * 256 + j];
    float val = mc[j] + ratio * d;
    out[j] = ct[j];
    out[256 + j] = rt[j];
    out[512 + (long)j * 4096 + pix] = val;
}

// ---------------- launch ----------------
extern "C" void kernel_launch(void* const* d_in, const int* in_sizes, int n_in,
                              void* d_out, int out_size) {
    const float* inputs = (const float*)d_in[0];
    const float* memory = (const float*)d_in[1];
    const float* K1     = (const float*)d_in[2];
    const float* K2     = (const float*)d_in[3];
    const float* D1     = (const float*)d_in[4];
    const float* D2     = (const float*)d_in[5];
    const float* CK     = (const float*)d_in[6];
    const float* REC    = (const float*)d_in[7];
    const int*   xp     = (const int*)d_in[8];
    const int*   yp     = (const int*)d_in[9];
    float* out = (float*)d_out;

    static int smem_set = 0;
    if (!smem_set) {
        cudaFuncSetAttribute(conv2_kernel, cudaFuncAttributeMaxDynamicSharedMemorySize,
                             (6240 + 9216) * 4);
        smem_set = 1;
    }

    conv1_kernel<<<dim3(64, 4), 256>>>(memory, K1);
    conv2_kernel<<<dim3(62, 2), 256, (6240 + 9216) * 4>>>(K2);
    gemv_d1_kernel<<<931, 128>>>(D1);
    rt_kernel<<<2, 128>>>(D2);
    qs_kernel<<<4, 128>>>(inputs, CK, REC);
    scores_kernel<<<128, 256>>>(memory);
    smax_kernel<<<1, 256>>>();
    trans_ct_kernel<<<dim3(128, 8), dim3(32, 8)>>>(memory, out);
    final_kernel<<<2, 128>>>(memory, REC, xp, yp, out);
}

// round 4
// speedup vs baseline: 1.5417x; 1.4964x over previous
#include <cuda_runtime.h>
#include <cuda_bf16.h>

#define NFLAT 238144   // 64*61*61

// ---------------- scratch (device globals; no allocation) ----------------
__device__ float g_out1p[4 * 4096 * 32];   // conv1 partials per ic-quarter
__device__ float g_c2[64 * 62 * 62];       // conv2 out, [oc][i][j]
__device__ float g_r128[128];
__device__ float g_rt[256];
__device__ float g_qt[256];
__device__ float g_st[256];
__device__ float g_d[256];                 // (mem_t - s_t) @ write_update
__device__ float g_scores[4096];
__device__ float g_smax[2];
__device__ float g_ct[256];

// ---------------- packed fp32x2 helpers ----------------
typedef unsigned long long ull;
__device__ __forceinline__ ull pack2(float lo, float hi) {
    ull r; asm("mov.b64 %0, {%1,%2};" : "=l"(r) : "f"(lo), "f"(hi)); return r;
}
__device__ __forceinline__ void unpack2(ull v, float& lo, float& hi) {
    asm("mov.b64 {%0,%1}, %2;" : "=f"(lo), "=f"(hi) : "l"(v));
}
__device__ __forceinline__ void fma2(ull& d, ull a, ull b) {
    asm("fma.rn.f32x2 %0, %1, %2, %0;" : "+l"(d) : "l"(a), "l"(b));
}

// ---------------- conv1: SAME 3x3, 256 -> 32, 64x64 ----------------
__global__ __launch_bounds__(256) void conv1_kernel(const float* __restrict__ mem,
                                                    const float* __restrict__ K1) {
    int h   = blockIdx.x;
    int icq = blockIdx.y;
    int tid = threadIdx.x;
    int pg  = tid & 15;
    int og  = tid >> 4;

    __shared__ float sIn[32 * 67];
    __shared__ float sW[3 * 32 * 32];

    ull acc[4] = {0ull, 0ull, 0ull, 0ull};

    for (int kh = 0; kh < 3; kh++) {
        int r = h + kh - 1;
        if (r < 0 || r > 63) continue;
        for (int ch = 0; ch < 2; ch++) {
            int ic0 = icq * 64 + ch * 32;
            __syncthreads();
            for (int t = tid; t < 32 * 66; t += 256) {
                int ic = t & 31;
                int c  = t >> 5;
                float v = 0.f;
                int col = c - 1;
                if (col >= 0 && col < 64) v = mem[(r * 64 + col) * 256 + ic0 + ic];
                sIn[ic * 67 + c] = v;
            }
            for (int t = tid; t < 3 * 32 * 32; t += 256) {
                int oc = t & 31;
                int ic = (t >> 5) & 31;
                int kw = t >> 10;
                sW[t] = K1[((kh * 3 + kw) * 256 + ic0 + ic) * 32 + oc];
            }
            __syncthreads();
#pragma unroll 4
            for (int ic = 0; ic < 32; ic++) {
                float xv[6];
#pragma unroll
                for (int c = 0; c < 6; c++) xv[c] = sIn[ic * 67 + pg * 4 + c];
                ull xb[6];
#pragma unroll
                for (int c = 0; c < 6; c++) xb[c] = pack2(xv[c], xv[c]);
#pragma unroll
                for (int kw = 0; kw < 3; kw++) {
                    ull w = *(const ull*)&sW[(kw * 32 + ic) * 32 + og * 2];
                    fma2(acc[0], xb[kw + 0], w);
                    fma2(acc[1], xb[kw + 1], w);
                    fma2(acc[2], xb[kw + 2], w);
                    fma2(acc[3], xb[kw + 3], w);
                }
            }
        }
    }
    float* dst = g_out1p + icq * 131072 + (h * 64) * 32;
#pragma unroll
    for (int a = 0; a < 4; a++) {
        float lo, hi;
        unpack2(acc[a], lo, hi);
        int px = pg * 4 + a;
        dst[px * 32 + og * 2 + 0] = lo;
        dst[px * 32 + og * 2 + 1] = hi;
    }
}

// ---------------- conv2: VALID 3x3, 32 -> 64 (+ zero all atomic targets) ----------------
__global__ __launch_bounds__(256) void conv2_kernel(const float* __restrict__ K2) {
    extern __shared__ float sm2[];
    float* sIn = sm2;                 // 3*32*65 = 6240
    float* sW  = sm2 + 6240;          // 9*32*32 = 9216

    int i    = blockIdx.x;
    int half = blockIdx.y;
    int tid  = threadIdx.x;
    if (half == 0) {
        if (i == 0) { g_rt[tid] = 0.f; g_qt[tid] = 0.f; }
        if (i == 1) { g_st[tid] = 0.f; g_d[tid]  = 0.f; }
        if (i == 2 && tid < 128) g_r128[tid] = 0.f;
    }

    int pxg = tid & 31;
    int ocg = tid >> 5;

    for (int t = tid; t < 3 * 64 * 32; t += 256) {
        int ic  = t & 31;
        int col = (t >> 5) & 63;
        int rr  = t >> 11;
        const float* p = g_out1p + ((i + rr) * 64 + col) * 32 + ic;
        sIn[(rr * 32 + ic) * 65 + col] = p[0] + p[131072] + p[262144] + p[393216];
    }
    for (int t = tid; t < 9 * 32 * 32; t += 256) {
        int ocl = t & 31;
        int ic  = (t >> 5) & 31;
        int kk  = t >> 10;
        sW[t] = K2[(kk * 32 + ic) * 64 + half * 32 + ocl];
    }
    __syncthreads();

    if (pxg < 31) {
        int px = pxg * 2;
        ull acc[2][2] = {{0ull, 0ull}, {0ull, 0ull}};
        for (int kh = 0; kh < 3; kh++) {
#pragma unroll 4
            for (int ic = 0; ic < 32; ic++) {
                float xv[4];
#pragma unroll
                for (int c = 0; c < 4; c++) xv[c] = sIn[(kh * 32 + ic) * 65 + px + c];
                ull xb[4];
#pragma unroll
                for (int c = 0; c < 4; c++) xb[c] = pack2(xv[c], xv[c]);
#pragma unroll
                for (int kw = 0; kw < 3; kw++) {
                    const ull* wp = (const ull*)&sW[((kh * 3 + kw) * 32 + ic) * 32 + ocg * 4];
                    ull w0 = wp[0], w1 = wp[1];
                    fma2(acc[0][0], xb[kw + 0], w0);
                    fma2(acc[0][1], xb[kw + 0], w1);
                    fma2(acc[1][0], xb[kw + 1], w0);
                    fma2(acc[1][1], xb[kw + 1], w1);
                }
            }
        }
#pragma unroll
        for (int a = 0; a < 2; a++)
#pragma unroll
            for (int b = 0; b < 2; b++) {
                float lo, hi;
                unpack2(acc[a][b], lo, hi);
                int oc = half * 32 + ocg * 4 + b * 2;
                g_c2[(oc + 0) * 3844 + i * 62 + px + a] = lo;
                g_c2[(oc + 1) * 3844 + i * 62 + px + a] = hi;
            }
    }
}

// ---------------- GEMV with fused pool: r128 += flat @ D1 (float4, 512 flats/blk) ----------------
__global__ __launch_bounds__(256) void gemv_d1_kernel(const float* __restrict__ D1) {
    __shared__ float sp[512];
    __shared__ float red[8 * 128];
    int fbase = blockIdx.x * 512;
    int n = NFLAT - fbase; if (n > 512) n = 512;
    for (int t = threadIdx.x; t < 512; t += 256) {
        float v = 0.f;
        if (t < n) {
            int f  = fbase + t;
            int j  = f % 61;
            int q  = f / 61;
            int ii = q % 61;
            int oc = q / 61;
            const float* p = &g_c2[oc * 3844 + ii * 62 + j];
            v = 0.25f * (p[0] + p[1] + p[62] + p[63]);
        }
        sp[t] = v;
    }
    __syncthreads();
    int kq   = threadIdx.x & 31;    // k quad (4 floats)
    int slot = threadIdx.x >> 5;    // 8 row slots
    const float4* D1v = (const float4*)D1;
    float4 acc = make_float4(0.f, 0.f, 0.f, 0.f);
    for (int f = slot; f < n; f += 8) {
        float s = sp[f];
        float4 dv = D1v[(long)(fbase + f) * 32 + kq];
        acc.x += s * dv.x; acc.y += s * dv.y; acc.z += s * dv.z; acc.w += s * dv.w;
    }
    float* rp = &red[slot * 128 + kq * 4];
    rp[0] = acc.x; rp[1] = acc.y; rp[2] = acc.z; rp[3] = acc.w;
    __syncthreads();
    if (threadIdx.x < 128) {
        float v = 0.f;
#pragma unroll
        for (int s = 0; s < 8; s++) v += red[s * 128 + threadIdx.x];
        atomicAdd(&g_r128[threadIdx.x], v);
    }
}

// ---------------- split-K: r_t (8 blocks) + s_t (8 blocks) ----------------
__global__ __launch_bounds__(256) void rtst_kernel(const float* __restrict__ D2,
                                                   const float* __restrict__ REC,
                                                   const float* __restrict__ inp) {
    __shared__ float a[16];
    int b = blockIdx.x;
    int j = threadIdx.x;
    if (b < 8) {
        int k0 = b * 16;
        if (j < 16) a[j] = g_r128[k0 + j];
        __syncthreads();
        float acc = 0.f;
#pragma unroll
        for (int u = 0; u < 16; u++) acc += a[u] * D2[(k0 + u) * 256 + j];
        atomicAdd(&g_rt[j], acc);
    } else {
        int k0 = (b - 8) * 16;
        if (j < 16) a[j] = inp[k0 + j];
        __syncthreads();
        float acc = 0.f;
#pragma unroll
        for (int u = 0; u < 16; u++) acc += a[u] * REC[(k0 + u) * 256 + j];
        atomicAdd(&g_st[j], acc);
    }
}

// ---------------- split-K: q_t (24 blocks) + d (16 blocks) ----------------
__global__ __launch_bounds__(256) void qd_kernel(const float* __restrict__ inp,
                                                 const float* __restrict__ CK,
                                                 const float* __restrict__ REC,
                                                 const float* __restrict__ mem,
                                                 const int* __restrict__ xp,
                                                 const int* __restrict__ yp) {
    __shared__ float a[16];
    int b = blockIdx.x;
    int j = threadIdx.x;
    if (b < 24) {
        int k0 = b * 16;
        if (j < 16) {
            int k = k0 + j;
            a[j] = (k < 128) ? inp[k] : g_rt[k - 128];
        }
        __syncthreads();
        float acc = 0.f;
#pragma unroll
        for (int u = 0; u < 16; u++) acc += a[u] * CK[(k0 + u) * 256 + j];
        atomicAdd(&g_qt[j], acc);
    } else {
        int c0 = (b - 24) * 16;
        int pix = xp[0] * 64 + yp[0];
        if (j < 16) a[j] = mem[pix * 256 + c0 + j] - g_st[c0 + j];
        __syncthreads();
        float acc = 0.f;
#pragma unroll
        for (int u = 0; u < 16; u++) acc += a[u] * REC[(128 + c0 + u) * 256 + j];
        atomicAdd(&g_d[j], acc);
    }
}

// ---------------- scores: q_t @ memory^T ----------------
__global__ __launch_bounds__(256) void scores_kernel(const float* __restrict__ mem) {
    __shared__ float q[256];
    int tid = threadIdx.x;
    q[tid] = g_qt[tid];
    __syncthreads();
    int warp = tid >> 5, lane = tid & 31;
    int pbase = blockIdx.x * 32 + warp * 4;
#pragma unroll
    for (int u = 0; u < 4; u++) {
        int p = pbase + u;
        float acc = 0.f;
#pragma unroll
        for (int t = 0; t < 8; t++) acc += q[lane + t * 32] * mem[p * 256 + lane + t * 32];
#pragma unroll
        for (int off = 16; off; off >>= 1) acc += __shfl_down_sync(0xFFFFFFFFu, acc, off);
        if (lane == 0) g_scores[p] = acc;
    }
}

// ---------------- softmax stats (+ zero g_ct) ----------------
__global__ __launch_bounds__(256) void smax_kernel() {
    __shared__ float red[256];
    int tid = threadIdx.x;
    g_ct[tid] = 0.f;
    float mx = -1e30f;
    for (int p = tid; p < 4096; p += 256) mx = fmaxf(mx, g_scores[p]);
    red[tid] = mx;
    __syncthreads();
    for (int s = 128; s; s >>= 1) { if (tid < s) red[tid] = fmaxf(red[tid], red[tid + s]); __syncthreads(); }
    mx = red[0];
    __syncthreads();
    float sum = 0.f;
    for (int p = tid; p < 4096; p += 256) sum += expf(g_scores[p] - mx);
    red[tid] = sum;
    __syncthreads();
    for (int s = 128; s; s >>= 1) { if (tid < s) red[tid] += red[tid + s]; __syncthreads(); }
    if (tid == 0) { g_smax[0] = mx; g_smax[1] = red[0]; }
}

// ---------------- fused transpose (new_mem) + c_t accumulation ----------------
__global__ void trans_ct_kernel(const float* __restrict__ mem, float* __restrict__ out) {
    __shared__ float tile[32][33];
    __shared__ float w[32];
    __shared__ float part[8][33];
    int p0 = blockIdx.x * 32, c0 = blockIdx.y * 32;
    int tx = threadIdx.x, ty = threadIdx.y;   // 32 x 8
#pragma unroll
    for (int r = 0; r < 32; r += 8) tile[ty + r][tx] = mem[(p0 + ty + r) * 256 + c0 + tx];
    if (ty == 0) w[tx] = expf(g_scores[p0 + tx] - g_smax[0]) / g_smax[1];
    __syncthreads();
#pragma unroll
    for (int r = 0; r < 32; r += 8)
        out[512 + (long)(c0 + ty + r) * 4096 + p0 + tx] = tile[tx][ty + r];
    float s = 0.f;
#pragma unroll
    for (int r = 0; r < 4; r++) s += w[ty + r * 8] * tile[ty + r * 8][tx];
    part[ty][tx] = s;
    __syncthreads();
    if (ty == 0) {
        float tot = 0.f;
#pragma unroll
        for (int y = 0; y < 8; y++) tot += part[y][tx];
        atomicAdd(&g_ct[c0 + tx], tot);
    }
}

// ---------------- final epilogue: ratio + small writes ----------------
__global__ __launch_bounds__(256) void final_kernel(const float* __restrict__ mem,
                                                    const int* __restrict__ xp,
                                                    const int* __restrict__ yp,
                                                    float* __restrict__ out) {
    __shared__ float red[256];
    __shared__ float ratio_s;
    int j = threadIdx.x;
    int pix = xp[0] * 64 + yp[0];
    float st = g_st[j], ct = g_ct[j], rt = g_rt[j];
    float mc = mem[pix * 256 + j];
    red[j] = st * ct;
    __syncthreads();
    for (int s = 128; s; s >>= 1) { if (j < s) red[j] += red[j + s]; __syncthreads(); }
    float local_imp = red[0];
    __syncthreads();
    red[j] = st * rt;
    __syncthreads();
    for (int s = 128; s; s >>= 1) { if (j < s) red[j] += red[j + s]; __syncthreads(); }
    if (j == 0) ratio_s = local_imp / (local_imp + red[0]);
    __syncthreads();
    float val = mc + ratio_s * g_d[j];
    out[j] = ct;
    out[256 + j] = rt;
    out[512 + (long)j * 4096 + pix] = val;
}

// ---------------- launch ----------------
extern "C" void kernel_launch(void* const* d_in, const int* in_sizes, int n_in,
                              void* d_out, int out_size) {
    const float* inputs = (const float*)d_in[0];
    const float* memory = (const float*)d_in[1];
    const float* K1     = (const float*)d_in[2];
    const float* K2     = (const float*)d_in[3];
    const float* D1     = (const float*)d_in[4];
    const float* D2     = (const float*)d_in[5];
    const float* CK     = (const float*)d_in[6];
    const float* REC    = (const float*)d_in[7];
    const int*   xp     = (const int*)d_in[8];
    const int*   yp     = (const int*)d_in[9];
    float* out = (float*)d_out;

    static int smem_set = 0;
    if (!smem_set) {
        cudaFuncSetAttribute(conv2_kernel, cudaFuncAttributeMaxDynamicSharedMemorySize,
                             (6240 + 9216) * 4);
        smem_set = 1;
    }

    conv1_kernel<<<dim3(64, 4), 256>>>(memory, K1);
    conv2_kernel<<<dim3(62, 2), 256, (6240 + 9216) * 4>>>(K2);
    gemv_d1_kernel<<<466, 256>>>(D1);
    rtst_kernel<<<16, 256>>>(D2, REC, inputs);
    qd_kernel<<<40, 256>>>(inputs, CK, REC, memory, xp, yp);
    scores_kernel<<<128, 256>>>(memory);
    smax_kernel<<<1, 256>>>();
    trans_ct_kernel<<<dim3(128, 8), dim3(32, 8)>>>(memory, out);
    final_kernel<<<1, 256>>>(memory, xp, yp, out);
}